// round 7
// baseline (speedup 1.0000x reference)
#include <cuda_runtime.h>
#include <cuda_bf16.h>
#include <cstdint>
#include <math.h>

#define BB 16
#define LL 2048
#define DDIM 64
#define FLOAT_MIN_F (-3.4028234663852886e38f)
#define PADE 72           // padded row length in bf16 elems
#define PADB 144          // padded row length in bytes (16B multiple)

// ---------------- device scratch ----------------
__device__ __nv_bfloat16 g_Qh[BB * LL * DDIM], g_Ql[BB * LL * DDIM];
__device__ __nv_bfloat16 g_Kh[BB * LL * DDIM], g_Kl[BB * LL * DDIM];
__device__ __nv_bfloat16 g_Vh[BB * LL * DDIM], g_Vl[BB * LL * DDIM];
__device__ float g_LM[(long long)LL * LL];    // max(log(mask),FMIN)  [q][k]
__device__ float g_LMT[(long long)LL * LL];   // transpose            [k][q]
__device__ float g_m[BB * LL], g_rz[BB * LL];

// ---------------- helpers ----------------
__device__ __forceinline__ uint32_t smem_u32(const void* p) {
    return (uint32_t)__cvta_generic_to_shared(p);
}
// pack two floats -> bf16x2 register, first arg in low half
__device__ __forceinline__ uint32_t pack_bf16x2(float lo, float hi) {
    uint32_t r;
    asm("cvt.rn.bf16x2.f32 %0, %1, %2;" : "=r"(r) : "f"(hi), "f"(lo));
    return r;
}
__device__ __forceinline__ float bf_lo(uint32_t h) { return __uint_as_float(h << 16); }
__device__ __forceinline__ float bf_hi(uint32_t h) { return __uint_as_float(h & 0xffff0000u); }

#define LDSM_X4(r, a) asm volatile( \
    "ldmatrix.sync.aligned.m8n8.x4.shared.b16 {%0,%1,%2,%3}, [%4];" \
    : "=r"((r)[0]), "=r"((r)[1]), "=r"((r)[2]), "=r"((r)[3]) : "r"(a))
#define LDSM_X2(r, a) asm volatile( \
    "ldmatrix.sync.aligned.m8n8.x2.shared.b16 {%0,%1}, [%2];" \
    : "=r"((r)[0]), "=r"((r)[1]) : "r"(a))
#define LDSM_X2T(r, a) asm volatile( \
    "ldmatrix.sync.aligned.m8n8.x2.trans.shared.b16 {%0,%1}, [%2];" \
    : "=r"((r)[0]), "=r"((r)[1]) : "r"(a))
#define MMA_BF16(d, a, b) asm volatile( \
    "mma.sync.aligned.m16n8k16.row.col.f32.bf16.bf16.f32 " \
    "{%0,%1,%2,%3}, {%4,%5,%6,%7}, {%8,%9}, {%0,%1,%2,%3};" \
    : "+f"((d)[0]), "+f"((d)[1]), "+f"((d)[2]), "+f"((d)[3]) \
    : "r"((a)[0]), "r"((a)[1]), "r"((a)[2]), "r"((a)[3]), "r"((b)[0]), "r"((b)[1]))

#define CP_ASYNC16(dst, src) asm volatile( \
    "cp.async.cg.shared.global [%0], [%1], 16;" :: "r"(dst), "l"(src))
#define CP_COMMIT() asm volatile("cp.async.commit_group;" ::: "memory")
#define CP_WAIT(n)  asm volatile("cp.async.wait_group %0;" :: "n"(n) : "memory")

__device__ __forceinline__ void mz_merge(float& m, float& z, float m2, float z2) {
    float mn = fmaxf(m, m2);
    z = z * __expf(m - mn) + z2 * __expf(m2 - mn);
    m = mn;
}

// ---------------- prep kernels ----------------
__global__ __launch_bounds__(256) void prep_lm(const float* __restrict__ mask) {
    __shared__ float t[32][33];
    const int q0 = blockIdx.y * 32, k0 = blockIdx.x * 32;
    for (int r = threadIdx.y; r < 32; r += 8) {
        float v = mask[(long long)(q0 + r) * LL + k0 + threadIdx.x];
        float lm = fmaxf(__logf(v), FLOAT_MIN_F);
        g_LM[(long long)(q0 + r) * LL + k0 + threadIdx.x] = lm;
        t[r][threadIdx.x] = lm;
    }
    __syncthreads();
    for (int r = threadIdx.y; r < 32; r += 8)
        g_LMT[(long long)(k0 + r) * LL + q0 + threadIdx.x] = t[threadIdx.x][r];
}

__global__ __launch_bounds__(256) void prep_split(const float* __restrict__ Q,
                                                  const float* __restrict__ K,
                                                  const float* __restrict__ V) {
    const float* src = blockIdx.y == 0 ? Q : (blockIdx.y == 1 ? K : V);
    uint32_t* h = (uint32_t*)(blockIdx.y == 0 ? g_Qh : (blockIdx.y == 1 ? g_Kh : g_Vh));
    uint32_t* l = (uint32_t*)(blockIdx.y == 0 ? g_Ql : (blockIdx.y == 1 ? g_Kl : g_Vl));
    const int i = blockIdx.x * 256 + threadIdx.x;   // float4 index (524288 total)
    float4 v = ((const float4*)src)[i];
    uint32_t h0 = pack_bf16x2(v.x, v.y);
    uint32_t h1 = pack_bf16x2(v.z, v.w);
    uint32_t l0 = pack_bf16x2(v.x - bf_lo(h0), v.y - bf_hi(h0));
    uint32_t l1 = pack_bf16x2(v.z - bf_lo(h1), v.w - bf_hi(h1));
    h[i * 2] = h0; h[i * 2 + 1] = h1;
    l[i * 2] = l0; l[i * 2 + 1] = l1;
}

// ---------------- phase 1: column stats via S^T = K @ Q^T ----------------
#define P1_KH 0
#define P1_KL 18432
#define P1_QH 36864
#define P1_QL 55296
#define P1_PM 73728
#define P1_PZ 74752
#define P1_RM 75776
#define P1_RZ 76288
#define P1_SMEM 76800

__global__ __launch_bounds__(256, 2) void p1_kernel() {
    extern __shared__ char smc[];
    const int tid = threadIdx.x, lane = tid & 31, wid = tid >> 5;
    const int wm = wid >> 1, wn = wid & 1;      // warp grid 4(M=k) x 2(N=q)
    const int b = blockIdx.y, k0 = blockIdx.x * 128;
    float* pm = (float*)(smc + P1_PM);
    float* pz = (float*)(smc + P1_PZ);
    float* rm = (float*)(smc + P1_RM);
    float* rzs = (float*)(smc + P1_RZ);

    const uint4* kh4 = (const uint4*)g_Kh;
    const uint4* kl4 = (const uint4*)g_Kl;
    for (int i = tid; i < 1024; i += 256) {
        int row = i >> 3, seg = i & 7;
        size_t gi = ((size_t)b * LL + k0 + row) * 8 + seg;
        *(uint4*)(smc + P1_KH + row * PADB + seg * 16) = kh4[gi];
        *(uint4*)(smc + P1_KL + row * PADB + seg * 16) = kl4[gi];
    }
    if (tid < 128) { rm[tid] = -INFINITY; rzs[tid] = 0.0f; }

    const uint32_t sb = smem_u32(smc);
    const int lr8 = lane & 7, lg = lane >> 3;
    const uint32_t a_lane = (uint32_t)(((lg & 1) * 8 + lr8) * PADB + (lg >> 1) * 16);
    const int l16 = lane & 15;
    const uint32_t b_lane = (uint32_t)((l16 & 7) * PADB + (l16 >> 3) * 16);
    const uint32_t aK = sb + P1_KH + (uint32_t)(wm * 32) * PADB + a_lane;
    const uint32_t bQ = sb + P1_QH + (uint32_t)(wn * 64) * PADB + b_lane;

    const uint4* qh4 = (const uint4*)g_Qh;
    const uint4* ql4 = (const uint4*)g_Ql;

    for (int qt = 0; qt < 16; qt++) {
        const int q0 = qt * 128;
        for (int i = tid; i < 1024; i += 256) {
            int row = i >> 3, seg = i & 7;
            size_t gi = ((size_t)b * LL + q0 + row) * 8 + seg;
            *(uint4*)(smc + P1_QH + row * PADB + seg * 16) = qh4[gi];
            *(uint4*)(smc + P1_QL + row * PADB + seg * 16) = ql4[gi];
        }
        __syncthreads();

        float acc[2][8][4];
#pragma unroll
        for (int mt = 0; mt < 2; mt++)
#pragma unroll
            for (int nt = 0; nt < 8; nt++)
#pragma unroll
                for (int r = 0; r < 4; r++) acc[mt][nt][r] = 0.0f;

#pragma unroll
        for (int ks = 0; ks < 4; ks++) {
            uint32_t aH[2][4], aL[2][4];
#pragma unroll
            for (int mt = 0; mt < 2; mt++) {
                LDSM_X4(aH[mt], aK + mt * 16 * PADB + ks * 32);
                LDSM_X4(aL[mt], aK + 18432 + mt * 16 * PADB + ks * 32);
            }
#pragma unroll
            for (int nt = 0; nt < 8; nt++) {
                uint32_t bH[2], bL[2];
                LDSM_X2(bH, bQ + nt * 8 * PADB + ks * 32);
                LDSM_X2(bL, bQ + 18432 + nt * 8 * PADB + ks * 32);
#pragma unroll
                for (int mt = 0; mt < 2; mt++) {
                    MMA_BF16(acc[mt][nt], aH[mt], bH);
                    MMA_BF16(acc[mt][nt], aH[mt], bL);
                    MMA_BF16(acc[mt][nt], aL[mt], bH);
                }
            }
        }

        // epilogue: s = acc/8 + LMT; per-k-row max & sum(exp)
#pragma unroll
        for (int mt = 0; mt < 2; mt++) {
#pragma unroll
            for (int h = 0; h < 2; h++) {
                const int krow = k0 + wm * 32 + mt * 16 + (lane >> 2) + h * 8;
                const float* lmp = g_LMT + (size_t)krow * LL + q0 + wn * 64 + (lane & 3) * 2;
                float mloc = -INFINITY;
#pragma unroll
                for (int nt = 0; nt < 8; nt++) {
                    float2 lm2 = *(const float2*)(lmp + nt * 8);
                    float s0 = acc[mt][nt][2 * h] * 0.125f + lm2.x;
                    float s1 = acc[mt][nt][2 * h + 1] * 0.125f + lm2.y;
                    acc[mt][nt][2 * h] = s0; acc[mt][nt][2 * h + 1] = s1;
                    mloc = fmaxf(mloc, fmaxf(s0, s1));
                }
                float zloc = 0.0f;
#pragma unroll
                for (int nt = 0; nt < 8; nt++)
                    zloc += __expf(acc[mt][nt][2 * h] - mloc) +
                            __expf(acc[mt][nt][2 * h + 1] - mloc);
#pragma unroll
                for (int off = 1; off <= 2; off <<= 1) {
                    float m2 = __shfl_xor_sync(0xffffffffu, mloc, off);
                    float z2 = __shfl_xor_sync(0xffffffffu, zloc, off);
                    mz_merge(mloc, zloc, m2, z2);
                }
                if ((lane & 3) == 0) {
                    int rrow = wm * 32 + mt * 16 + (lane >> 2) + h * 8;
                    pm[wn * 128 + rrow] = mloc;
                    pz[wn * 128 + rrow] = zloc;
                }
            }
        }
        __syncthreads();
        if (tid < 128) {
            mz_merge(rm[tid], rzs[tid], pm[tid], pz[tid]);
            mz_merge(rm[tid], rzs[tid], pm[128 + tid], pz[128 + tid]);
        }
        __syncthreads();
    }
    if (tid < 128) {
        g_m[b * LL + k0 + tid] = rm[tid];
        g_rz[b * LL + k0 + tid] = 1.0f / rzs[tid];
    }
}

// ---------------- phase 2: recompute S, P = exp(S-m)*rz, O += P@V ----------------
// 512 threads, 16 warps: 8(M=16q each) x 2(N=k-half). Double-buffered cp.async.
#define P2_QH 0
#define P2_QL 18432
#define P2_BUF0 36864
#define P2_BUFSZ 73728            // KH 0, KL 18432, VH 36864, VL 55296
#define P2_MRZ 184320             // per buf: ms (512B) + rz (512B)
#define P2_SMEM 186368
#define P2_OB 36864               // output combine buffer (aliases buf0, post-loop)

__global__ __launch_bounds__(512, 1) void p2_kernel(float* __restrict__ out) {
    extern __shared__ char smc[];
    const int tid = threadIdx.x, lane = tid & 31, wid = tid >> 5;
    const int wm = wid >> 1, wn = wid & 1;      // 8(M=q, 16 rows) x 2(N=k-half)
    const int b = blockIdx.y, q0 = blockIdx.x * 128;
    const uint32_t sb = smem_u32(smc);

    // Q tile (async, lands with first chunk's group)
    for (int i = tid; i < 1024; i += 512) {
        int row = i >> 3, seg = i & 7;
        size_t go = (((size_t)b * LL + q0 + row) * 64) * 2 + seg * 16;
        uint32_t d = sb + row * PADB + seg * 16;
        CP_ASYNC16(d + P2_QH, (const char*)g_Qh + go);
        CP_ASYNC16(d + P2_QL, (const char*)g_Ql + go);
    }

    // chunk prefetch: K/V hi+lo and m/rz into buffer `buf`
    auto prefetch = [&](int kc2, int buf) {
        const uint32_t db = sb + P2_BUF0 + buf * P2_BUFSZ;
        for (int i = tid; i < 1024; i += 512) {
            int row = i >> 3, seg = i & 7;
            size_t go = (((size_t)b * LL + kc2 * 128 + row) * 64) * 2 + seg * 16;
            uint32_t d = db + row * PADB + seg * 16;
            CP_ASYNC16(d + 0,     (const char*)g_Kh + go);
            CP_ASYNC16(d + 18432, (const char*)g_Kl + go);
            CP_ASYNC16(d + 36864, (const char*)g_Vh + go);
            CP_ASYNC16(d + 55296, (const char*)g_Vl + go);
        }
        if (tid < 32) {
            uint32_t d = sb + P2_MRZ + buf * 1024 + tid * 16;
            CP_ASYNC16(d,       (const char*)(g_m  + b * LL + kc2 * 128) + tid * 16);
            CP_ASYNC16(d + 512, (const char*)(g_rz + b * LL + kc2 * 128) + tid * 16);
        }
        CP_COMMIT();
    };
    prefetch(0, 0);

    const int lr8 = lane & 7, lg = lane >> 3;
    const uint32_t a_lane = (uint32_t)(((lg & 1) * 8 + lr8) * PADB + (lg >> 1) * 16);
    const int l16 = lane & 15;
    const uint32_t b_lane = (uint32_t)((l16 & 7) * PADB + (l16 >> 3) * 16);
    const uint32_t aQ = sb + P2_QH + (uint32_t)(wm * 16) * PADB + a_lane;

    float oacc[8][4];
#pragma unroll
    for (int nt = 0; nt < 8; nt++)
#pragma unroll
        for (int r = 0; r < 4; r++) oacc[nt][r] = 0.0f;

    for (int kc = 0; kc < 16; kc++) {
        const int k0 = kc * 128;
        const int buf = kc & 1;
        if (kc + 1 < 16) { prefetch(kc + 1, buf ^ 1); CP_WAIT(1); }
        else             { CP_WAIT(0); }
        __syncthreads();   // chunk kc visible to all warps

        const uint32_t bufb = sb + P2_BUF0 + buf * P2_BUFSZ;
        const uint32_t bK = bufb + (uint32_t)(wn * 64) * PADB + b_lane;
        const uint32_t vV = bufb + 36864 + (uint32_t)(wn * 64) * PADB + (uint32_t)(l16 * PADB);
        const float* msp  = (const float*)(smc + P2_MRZ + buf * 1024);
        const float* rzsp = msp + 128;

        float sacc[8][4];
#pragma unroll
        for (int nt = 0; nt < 8; nt++)
#pragma unroll
            for (int r = 0; r < 4; r++) sacc[nt][r] = 0.0f;

#pragma unroll
        for (int ks = 0; ks < 4; ks++) {
            uint32_t aH[4], aL[4];
            LDSM_X4(aH, aQ + ks * 32);
            LDSM_X4(aL, aQ + 18432 + ks * 32);
#pragma unroll
            for (int nt = 0; nt < 8; nt++) {
                uint32_t bH[2], bL[2];
                LDSM_X2(bH, bK + nt * 8 * PADB + ks * 32);
                LDSM_X2(bL, bK + 18432 + nt * 8 * PADB + ks * 32);
                MMA_BF16(sacc[nt], aH, bH);
                MMA_BF16(sacc[nt], aH, bL);
                MMA_BF16(sacc[nt], aL, bH);
            }
        }

        // fused softmax-apply + PV, one k16 group at a time
#pragma unroll
        for (int kg = 0; kg < 4; kg++) {
            uint32_t pfh[4], pfl[4];
            const int r0 = q0 + wm * 16 + (lane >> 2);
#pragma unroll
            for (int ti = 0; ti < 2; ti++) {
                const int t = 2 * kg + ti;
                const int kl = wn * 64 + t * 8 + (lane & 3) * 2;
                float m0 = msp[kl], m1 = msp[kl + 1];
                float z0 = rzsp[kl], z1 = rzsp[kl + 1];
                const float* lmA = g_LM + (size_t)r0 * LL + k0 + kl;
                float2 lA = *(const float2*)lmA;
                float2 lB = *(const float2*)(lmA + 8 * LL);
                float p00 = __expf(sacc[t][0] * 0.125f + lA.x - m0) * z0;
                float p01 = __expf(sacc[t][1] * 0.125f + lA.y - m1) * z1;
                float p10 = __expf(sacc[t][2] * 0.125f + lB.x - m0) * z0;
                float p11 = __expf(sacc[t][3] * 0.125f + lB.y - m1) * z1;
                uint32_t h0 = pack_bf16x2(p00, p01);
                uint32_t h1 = pack_bf16x2(p10, p11);
                pfh[ti * 2] = h0;
                pfh[ti * 2 + 1] = h1;
                pfl[ti * 2] = pack_bf16x2(p00 - bf_lo(h0), p01 - bf_hi(h0));
                pfl[ti * 2 + 1] = pack_bf16x2(p10 - bf_lo(h1), p11 - bf_hi(h1));
            }
#pragma unroll
            for (int nt = 0; nt < 8; nt++) {
                uint32_t vh[2], vl[2];
                LDSM_X2T(vh, vV + kg * 16 * PADB + nt * 16);
                LDSM_X2T(vl, vV + 18432 + kg * 16 * PADB + nt * 16);
                MMA_BF16(oacc[nt], pfh, vh);
                MMA_BF16(oacc[nt], pfh, vl);
                MMA_BF16(oacc[nt], pfl, vh);
            }
        }
        __syncthreads();   // all warps done with buf before next prefetch overwrites it
    }

    // combine the two k-half warps and store
    float* ob = (float*)(smc + P2_OB);
    if (wn == 1) {
#pragma unroll
        for (int nt = 0; nt < 8; nt++)
#pragma unroll
            for (int h = 0; h < 2; h++) {
                int r = wm * 16 + (lane >> 2) + h * 8;
                *(float2*)&ob[r * 66 + nt * 8 + (lane & 3) * 2] =
                    make_float2(oacc[nt][2 * h], oacc[nt][2 * h + 1]);
            }
    }
    __syncthreads();
    if (wn == 0) {
#pragma unroll
        for (int nt = 0; nt < 8; nt++)
#pragma unroll
            for (int h = 0; h < 2; h++) {
                int r = wm * 16 + (lane >> 2) + h * 8;
                float2 o2 = *(float2*)&ob[r * 66 + nt * 8 + (lane & 3) * 2];
                float2 res = make_float2(oacc[nt][2 * h] + o2.x,
                                         oacc[nt][2 * h + 1] + o2.y);
                *(float2*)&out[((size_t)b * LL + q0 + r) * DDIM + nt * 8 + (lane & 3) * 2] = res;
            }
    }
}

// ---------------------------------------------------------------------------
extern "C" void kernel_launch(void* const* d_in, const int* in_sizes, int n_in,
                              void* d_out, int out_size) {
    const float* Q = (const float*)d_in[0];
    const float* K = (const float*)d_in[1];
    const float* V = (const float*)d_in[2];
    const float* mask = (const float*)d_in[3];
    float* out = (float*)d_out;

    cudaFuncSetAttribute(p1_kernel, cudaFuncAttributeMaxDynamicSharedMemorySize, P1_SMEM);
    cudaFuncSetAttribute(p2_kernel, cudaFuncAttributeMaxDynamicSharedMemorySize, P2_SMEM);

    prep_lm<<<dim3(LL / 32, LL / 32), dim3(32, 8)>>>(mask);
    prep_split<<<dim3((BB * LL * DDIM) / 4 / 256, 3), 256>>>(Q, K, V);

    p1_kernel<<<dim3(LL / 128, BB), 256, P1_SMEM>>>();
    p2_kernel<<<dim3(LL / 128, BB), 512, P2_SMEM>>>(out);
}

// round 8
// speedup vs baseline: 1.0598x; 1.0598x over previous
#include <cuda_runtime.h>
#include <cuda_bf16.h>
#include <cstdint>
#include <math.h>

#define BB 16
#define LL 2048
#define DDIM 64
#define FLOAT_MIN_F (-3.4028234663852886e38f)
#define PADE 72           // padded row length in bf16 elems
#define PADB 144          // padded row length in bytes (16B multiple)

// ---------------- device scratch ----------------
__device__ __nv_bfloat16 g_Qh[BB * LL * DDIM], g_Ql[BB * LL * DDIM];
__device__ __nv_bfloat16 g_Kh[BB * LL * DDIM], g_Kl[BB * LL * DDIM];
__device__ __nv_bfloat16 g_Vh[BB * LL * DDIM], g_Vl[BB * LL * DDIM];
__device__ float g_LM[(long long)LL * LL];    // max(log(mask),FMIN)  [q][k]
__device__ float g_LMT[(long long)LL * LL];   // transpose            [k][q]
__device__ float g_m[BB * LL], g_rz[BB * LL];

// ---------------- helpers ----------------
__device__ __forceinline__ uint32_t smem_u32(const void* p) {
    return (uint32_t)__cvta_generic_to_shared(p);
}
// pack two floats -> bf16x2 register, first arg in low half
__device__ __forceinline__ uint32_t pack_bf16x2(float lo, float hi) {
    uint32_t r;
    asm("cvt.rn.bf16x2.f32 %0, %1, %2;" : "=r"(r) : "f"(hi), "f"(lo));
    return r;
}
__device__ __forceinline__ float bf_lo(uint32_t h) { return __uint_as_float(h << 16); }
__device__ __forceinline__ float bf_hi(uint32_t h) { return __uint_as_float(h & 0xffff0000u); }

#define LDSM_X4(r, a) asm volatile( \
    "ldmatrix.sync.aligned.m8n8.x4.shared.b16 {%0,%1,%2,%3}, [%4];" \
    : "=r"((r)[0]), "=r"((r)[1]), "=r"((r)[2]), "=r"((r)[3]) : "r"(a))
#define LDSM_X2(r, a) asm volatile( \
    "ldmatrix.sync.aligned.m8n8.x2.shared.b16 {%0,%1}, [%2];" \
    : "=r"((r)[0]), "=r"((r)[1]) : "r"(a))
#define LDSM_X2T(r, a) asm volatile( \
    "ldmatrix.sync.aligned.m8n8.x2.trans.shared.b16 {%0,%1}, [%2];" \
    : "=r"((r)[0]), "=r"((r)[1]) : "r"(a))
#define MMA_BF16(d, a, b) asm volatile( \
    "mma.sync.aligned.m16n8k16.row.col.f32.bf16.bf16.f32 " \
    "{%0,%1,%2,%3}, {%4,%5,%6,%7}, {%8,%9}, {%0,%1,%2,%3};" \
    : "+f"((d)[0]), "+f"((d)[1]), "+f"((d)[2]), "+f"((d)[3]) \
    : "r"((a)[0]), "r"((a)[1]), "r"((a)[2]), "r"((a)[3]), "r"((b)[0]), "r"((b)[1]))

#define CP_ASYNC16(dst, src) asm volatile( \
    "cp.async.cg.shared.global [%0], [%1], 16;" :: "r"(dst), "l"(src))
#define CP_COMMIT() asm volatile("cp.async.commit_group;" ::: "memory")
#define CP_WAIT(n)  asm volatile("cp.async.wait_group %0;" :: "n"(n) : "memory")

__device__ __forceinline__ void mz_merge(float& m, float& z, float m2, float z2) {
    float mn = fmaxf(m, m2);
    z = z * __expf(m - mn) + z2 * __expf(m2 - mn);
    m = mn;
}

// ---------------- prep kernels ----------------
__global__ __launch_bounds__(256) void prep_lm(const float* __restrict__ mask) {
    __shared__ float t[32][33];
    const int q0 = blockIdx.y * 32, k0 = blockIdx.x * 32;
    for (int r = threadIdx.y; r < 32; r += 8) {
        float v = mask[(long long)(q0 + r) * LL + k0 + threadIdx.x];
        float lm = fmaxf(__logf(v), FLOAT_MIN_F);
        g_LM[(long long)(q0 + r) * LL + k0 + threadIdx.x] = lm;
        t[r][threadIdx.x] = lm;
    }
    __syncthreads();
    for (int r = threadIdx.y; r < 32; r += 8)
        g_LMT[(long long)(k0 + r) * LL + q0 + threadIdx.x] = t[threadIdx.x][r];
}

__global__ __launch_bounds__(256) void prep_split(const float* __restrict__ Q,
                                                  const float* __restrict__ K,
                                                  const float* __restrict__ V) {
    const float* src = blockIdx.y == 0 ? Q : (blockIdx.y == 1 ? K : V);
    uint32_t* h = (uint32_t*)(blockIdx.y == 0 ? g_Qh : (blockIdx.y == 1 ? g_Kh : g_Vh));
    uint32_t* l = (uint32_t*)(blockIdx.y == 0 ? g_Ql : (blockIdx.y == 1 ? g_Kl : g_Vl));
    const int i = blockIdx.x * 256 + threadIdx.x;   // float4 index (524288 total)
    float4 v = ((const float4*)src)[i];
    uint32_t h0 = pack_bf16x2(v.x, v.y);
    uint32_t h1 = pack_bf16x2(v.z, v.w);
    uint32_t l0 = pack_bf16x2(v.x - bf_lo(h0), v.y - bf_hi(h0));
    uint32_t l1 = pack_bf16x2(v.z - bf_lo(h1), v.w - bf_hi(h1));
    h[i * 2] = h0; h[i * 2 + 1] = h1;
    l[i * 2] = l0; l[i * 2 + 1] = l1;
}

// ---------------- phase 1: column stats via S^T = K @ Q^T ----------------
// K resident; Q hi/lo double-buffered via cp.async.
// smem: K 0..36864 (KH 0, KL 18432); Q buf0 36864; Q buf1 73728; red 110592.
#define P1_K 0
#define P1_QB0 36864
#define P1_QBSZ 36864            // QH 0, QL 18432 within buffer
#define P1_PM 110592
#define P1_PZ 111616
#define P1_RM 112640
#define P1_RZ 113152
#define P1_SMEM 113664

__global__ __launch_bounds__(256, 2) void p1_kernel() {
    extern __shared__ char smc[];
    const int tid = threadIdx.x, lane = tid & 31, wid = tid >> 5;
    const int wm = wid >> 1, wn = wid & 1;      // warp grid 4(M=k) x 2(N=q)
    const int b = blockIdx.y, k0 = blockIdx.x * 128;
    float* pm = (float*)(smc + P1_PM);
    float* pz = (float*)(smc + P1_PZ);
    float* rm = (float*)(smc + P1_RM);
    float* rzs = (float*)(smc + P1_RZ);
    const uint32_t sb = smem_u32(smc);

    // K tile hi/lo via cp.async (joins first Q group)
    for (int i = tid; i < 1024; i += 256) {
        int row = i >> 3, seg = i & 7;
        size_t go = (((size_t)b * LL + k0 + row) * 64) * 2 + seg * 16;
        uint32_t d = sb + P1_K + row * PADB + seg * 16;
        CP_ASYNC16(d,         (const char*)g_Kh + go);
        CP_ASYNC16(d + 18432, (const char*)g_Kl + go);
    }

    auto prefetchQ = [&](int qt, int buf) {
        const uint32_t db = sb + P1_QB0 + buf * P1_QBSZ;
        for (int i = tid; i < 1024; i += 256) {
            int row = i >> 3, seg = i & 7;
            size_t go = (((size_t)b * LL + qt * 128 + row) * 64) * 2 + seg * 16;
            uint32_t d = db + row * PADB + seg * 16;
            CP_ASYNC16(d,         (const char*)g_Qh + go);
            CP_ASYNC16(d + 18432, (const char*)g_Ql + go);
        }
        CP_COMMIT();
    };
    prefetchQ(0, 0);
    if (tid < 128) { rm[tid] = -INFINITY; rzs[tid] = 0.0f; }

    const int lr8 = lane & 7, lg = lane >> 3;
    const uint32_t a_lane = (uint32_t)(((lg & 1) * 8 + lr8) * PADB + (lg >> 1) * 16);
    const int l16 = lane & 15;
    const uint32_t b_lane = (uint32_t)((l16 & 7) * PADB + (l16 >> 3) * 16);
    const uint32_t aK = sb + P1_K + (uint32_t)(wm * 32) * PADB + a_lane;

    for (int qt = 0; qt < 16; qt++) {
        const int q0 = qt * 128;
        const int buf = qt & 1;
        if (qt + 1 < 16) { prefetchQ(qt + 1, buf ^ 1); CP_WAIT(1); }
        else             { CP_WAIT(0); }
        __syncthreads();

        const uint32_t bQ = sb + P1_QB0 + buf * P1_QBSZ + (uint32_t)(wn * 64) * PADB + b_lane;

        float acc[2][8][4];
#pragma unroll
        for (int mt = 0; mt < 2; mt++)
#pragma unroll
            for (int nt = 0; nt < 8; nt++)
#pragma unroll
                for (int r = 0; r < 4; r++) acc[mt][nt][r] = 0.0f;

#pragma unroll
        for (int ks = 0; ks < 4; ks++) {
            uint32_t aH[2][4], aL[2][4];
#pragma unroll
            for (int mt = 0; mt < 2; mt++) {
                LDSM_X4(aH[mt], aK + mt * 16 * PADB + ks * 32);
                LDSM_X4(aL[mt], aK + 18432 + mt * 16 * PADB + ks * 32);
            }
#pragma unroll
            for (int nt = 0; nt < 8; nt++) {
                uint32_t bH[2], bL[2];
                LDSM_X2(bH, bQ + nt * 8 * PADB + ks * 32);
                LDSM_X2(bL, bQ + 18432 + nt * 8 * PADB + ks * 32);
#pragma unroll
                for (int mt = 0; mt < 2; mt++) {
                    MMA_BF16(acc[mt][nt], aH[mt], bH);
                    MMA_BF16(acc[mt][nt], aH[mt], bL);
                    MMA_BF16(acc[mt][nt], aL[mt], bH);
                }
            }
        }

        // epilogue: s = acc/8 + LMT; per-k-row max & sum(exp)
#pragma unroll
        for (int mt = 0; mt < 2; mt++) {
#pragma unroll
            for (int h = 0; h < 2; h++) {
                const int krow = k0 + wm * 32 + mt * 16 + (lane >> 2) + h * 8;
                const float* lmp = g_LMT + (size_t)krow * LL + q0 + wn * 64 + (lane & 3) * 2;
                float mloc = -INFINITY;
#pragma unroll
                for (int nt = 0; nt < 8; nt++) {
                    float2 lm2 = *(const float2*)(lmp + nt * 8);
                    float s0 = acc[mt][nt][2 * h] * 0.125f + lm2.x;
                    float s1 = acc[mt][nt][2 * h + 1] * 0.125f + lm2.y;
                    acc[mt][nt][2 * h] = s0; acc[mt][nt][2 * h + 1] = s1;
                    mloc = fmaxf(mloc, fmaxf(s0, s1));
                }
                float zloc = 0.0f;
#pragma unroll
                for (int nt = 0; nt < 8; nt++)
                    zloc += __expf(acc[mt][nt][2 * h] - mloc) +
                            __expf(acc[mt][nt][2 * h + 1] - mloc);
#pragma unroll
                for (int off = 1; off <= 2; off <<= 1) {
                    float m2 = __shfl_xor_sync(0xffffffffu, mloc, off);
                    float z2 = __shfl_xor_sync(0xffffffffu, zloc, off);
                    mz_merge(mloc, zloc, m2, z2);
                }
                if ((lane & 3) == 0) {
                    int rrow = wm * 32 + mt * 16 + (lane >> 2) + h * 8;
                    pm[wn * 128 + rrow] = mloc;
                    pz[wn * 128 + rrow] = zloc;
                }
            }
        }
        __syncthreads();
        if (tid < 128) {
            mz_merge(rm[tid], rzs[tid], pm[tid], pz[tid]);
            mz_merge(rm[tid], rzs[tid], pm[128 + tid], pz[128 + tid]);
        }
    }
    __syncthreads();
    if (tid < 128) {
        g_m[b * LL + k0 + tid] = rm[tid];
        g_rz[b * LL + k0 + tid] = 1.0f / rzs[tid];
    }
}

// ---------------- phase 2: recompute S, P = exp(S-m)*rz, O += P@V ----------------
// 256 threads, 8 warps: 4(M=32q each) x 2(N=k-half). Double-buffered cp.async.
#define P2_QH 0
#define P2_QL 18432
#define P2_BUF0 36864
#define P2_BUFSZ 73728            // KH 0, KL 18432, VH 36864, VL 55296
#define P2_MRZ 184320             // per buf: ms (512B) + rz (512B)
#define P2_SMEM 186368
#define P2_OB 36864               // output combine buffer (aliases buf0, post-loop)

__global__ __launch_bounds__(256, 1) void p2_kernel(float* __restrict__ out) {
    extern __shared__ char smc[];
    const int tid = threadIdx.x, lane = tid & 31, wid = tid >> 5;
    const int wm = wid >> 1, wn = wid & 1;      // 4(M=q) x 2(N=k-half)
    const int b = blockIdx.y, q0 = blockIdx.x * 128;
    const uint32_t sb = smem_u32(smc);

    // Q tile (async, lands with first chunk's group)
    for (int i = tid; i < 1024; i += 256) {
        int row = i >> 3, seg = i & 7;
        size_t go = (((size_t)b * LL + q0 + row) * 64) * 2 + seg * 16;
        uint32_t d = sb + row * PADB + seg * 16;
        CP_ASYNC16(d + P2_QH, (const char*)g_Qh + go);
        CP_ASYNC16(d + P2_QL, (const char*)g_Ql + go);
    }

    // chunk prefetch: K/V hi+lo and m/rz into buffer `buf`
    auto prefetch = [&](int kc2, int buf) {
        const uint32_t db = sb + P2_BUF0 + buf * P2_BUFSZ;
        for (int i = tid; i < 1024; i += 256) {
            int row = i >> 3, seg = i & 7;
            size_t go = (((size_t)b * LL + kc2 * 128 + row) * 64) * 2 + seg * 16;
            uint32_t d = db + row * PADB + seg * 16;
            CP_ASYNC16(d + 0,     (const char*)g_Kh + go);
            CP_ASYNC16(d + 18432, (const char*)g_Kl + go);
            CP_ASYNC16(d + 36864, (const char*)g_Vh + go);
            CP_ASYNC16(d + 55296, (const char*)g_Vl + go);
        }
        if (tid < 32) {
            uint32_t d = sb + P2_MRZ + buf * 1024 + tid * 16;
            CP_ASYNC16(d,       (const char*)(g_m  + b * LL + kc2 * 128) + tid * 16);
            CP_ASYNC16(d + 512, (const char*)(g_rz + b * LL + kc2 * 128) + tid * 16);
        }
        CP_COMMIT();
    };
    prefetch(0, 0);

    const int lr8 = lane & 7, lg = lane >> 3;
    const uint32_t a_lane = (uint32_t)(((lg & 1) * 8 + lr8) * PADB + (lg >> 1) * 16);
    const int l16 = lane & 15;
    const uint32_t b_lane = (uint32_t)((l16 & 7) * PADB + (l16 >> 3) * 16);
    const uint32_t aQ = sb + P2_QH + (uint32_t)(wm * 32) * PADB + a_lane;

    float oacc[2][8][4];
#pragma unroll
    for (int mt = 0; mt < 2; mt++)
#pragma unroll
        for (int nt = 0; nt < 8; nt++)
#pragma unroll
            for (int r = 0; r < 4; r++) oacc[mt][nt][r] = 0.0f;

    for (int kc = 0; kc < 16; kc++) {
        const int k0 = kc * 128;
        const int buf = kc & 1;
        if (kc + 1 < 16) { prefetch(kc + 1, buf ^ 1); CP_WAIT(1); }
        else             { CP_WAIT(0); }
        __syncthreads();   // chunk kc visible to all warps

        const uint32_t bufb = sb + P2_BUF0 + buf * P2_BUFSZ;
        const uint32_t bK = bufb + (uint32_t)(wn * 64) * PADB + b_lane;
        const uint32_t vV = bufb + 36864 + (uint32_t)(wn * 64) * PADB + (uint32_t)(l16 * PADB);
        const float* msp  = (const float*)(smc + P2_MRZ + buf * 1024);
        const float* rzsp = msp + 128;

        float sacc[2][8][4];
#pragma unroll
        for (int mt = 0; mt < 2; mt++)
#pragma unroll
            for (int nt = 0; nt < 8; nt++)
#pragma unroll
                for (int r = 0; r < 4; r++) sacc[mt][nt][r] = 0.0f;

#pragma unroll
        for (int ks = 0; ks < 4; ks++) {
            uint32_t aH[2][4], aL[2][4];
#pragma unroll
            for (int mt = 0; mt < 2; mt++) {
                LDSM_X4(aH[mt], aQ + mt * 16 * PADB + ks * 32);
                LDSM_X4(aL[mt], aQ + 18432 + mt * 16 * PADB + ks * 32);
            }
#pragma unroll
            for (int nt = 0; nt < 8; nt++) {
                uint32_t bH[2], bL[2];
                LDSM_X2(bH, bK + nt * 8 * PADB + ks * 32);
                LDSM_X2(bL, bK + 18432 + nt * 8 * PADB + ks * 32);
#pragma unroll
                for (int mt = 0; mt < 2; mt++) {
                    MMA_BF16(sacc[mt][nt], aH[mt], bH);
                    MMA_BF16(sacc[mt][nt], aH[mt], bL);
                    MMA_BF16(sacc[mt][nt], aL[mt], bH);
                }
            }
        }

        // fused softmax-apply + PV, one k16 group at a time
#pragma unroll
        for (int kg = 0; kg < 4; kg++) {
            uint32_t pfh[2][4], pfl[2][4];
#pragma unroll
            for (int mt = 0; mt < 2; mt++) {
                const int r0 = q0 + wm * 32 + mt * 16 + (lane >> 2);
#pragma unroll
                for (int ti = 0; ti < 2; ti++) {
                    const int t = 2 * kg + ti;
                    const int kl = wn * 64 + t * 8 + (lane & 3) * 2;
                    float m0 = msp[kl], m1 = msp[kl + 1];
                    float z0 = rzsp[kl], z1 = rzsp[kl + 1];
                    const float* lmA = g_LM + (size_t)r0 * LL + k0 + kl;
                    float2 lA = *(const float2*)lmA;
                    float2 lB = *(const float2*)(lmA + 8 * LL);
                    float p00 = __expf(sacc[mt][t][0] * 0.125f + lA.x - m0) * z0;
                    float p01 = __expf(sacc[mt][t][1] * 0.125f + lA.y - m1) * z1;
                    float p10 = __expf(sacc[mt][t][2] * 0.125f + lB.x - m0) * z0;
                    float p11 = __expf(sacc[mt][t][3] * 0.125f + lB.y - m1) * z1;
                    uint32_t h0 = pack_bf16x2(p00, p01);
                    uint32_t h1 = pack_bf16x2(p10, p11);
                    pfh[mt][ti * 2] = h0;
                    pfh[mt][ti * 2 + 1] = h1;
                    pfl[mt][ti * 2] = pack_bf16x2(p00 - bf_lo(h0), p01 - bf_hi(h0));
                    pfl[mt][ti * 2 + 1] = pack_bf16x2(p10 - bf_lo(h1), p11 - bf_hi(h1));
                }
            }
#pragma unroll
            for (int nt = 0; nt < 8; nt++) {
                uint32_t vh[2], vl[2];
                LDSM_X2T(vh, vV + kg * 16 * PADB + nt * 16);
                LDSM_X2T(vl, vV + 18432 + kg * 16 * PADB + nt * 16);
#pragma unroll
                for (int mt = 0; mt < 2; mt++) {
                    MMA_BF16(oacc[mt][nt], pfh[mt], vh);
                    MMA_BF16(oacc[mt][nt], pfh[mt], vl);
                    MMA_BF16(oacc[mt][nt], pfl[mt], vh);
                }
            }
        }
        __syncthreads();   // all warps done with buf before next prefetch overwrites it
    }

    // combine the two k-half warps and store
    float* ob = (float*)(smc + P2_OB);
    if (wn == 1) {
#pragma unroll
        for (int mt = 0; mt < 2; mt++)
#pragma unroll
            for (int nt = 0; nt < 8; nt++)
#pragma unroll
                for (int h = 0; h < 2; h++) {
                    int r = wm * 32 + mt * 16 + (lane >> 2) + h * 8;
                    *(float2*)&ob[r * 66 + nt * 8 + (lane & 3) * 2] =
                        make_float2(oacc[mt][nt][2 * h], oacc[mt][nt][2 * h + 1]);
                }
    }
    __syncthreads();
    if (wn == 0) {
#pragma unroll
        for (int mt = 0; mt < 2; mt++)
#pragma unroll
            for (int nt = 0; nt < 8; nt++)
#pragma unroll
                for (int h = 0; h < 2; h++) {
                    int r = wm * 32 + mt * 16 + (lane >> 2) + h * 8;
                    float2 o2 = *(float2*)&ob[r * 66 + nt * 8 + (lane & 3) * 2];
                    float2 res = make_float2(oacc[mt][nt][2 * h] + o2.x,
                                             oacc[mt][nt][2 * h + 1] + o2.y);
                    *(float2*)&out[((size_t)b * LL + q0 + r) * DDIM + nt * 8 + (lane & 3) * 2] = res;
                }
    }
}

// ---------------------------------------------------------------------------
extern "C" void kernel_launch(void* const* d_in, const int* in_sizes, int n_in,
                              void* d_out, int out_size) {
    const float* Q = (const float*)d_in[0];
    const float* K = (const float*)d_in[1];
    const float* V = (const float*)d_in[2];
    const float* mask = (const float*)d_in[3];
    float* out = (float*)d_out;

    cudaFuncSetAttribute(p1_kernel, cudaFuncAttributeMaxDynamicSharedMemorySize, P1_SMEM);
    cudaFuncSetAttribute(p2_kernel, cudaFuncAttributeMaxDynamicSharedMemorySize, P2_SMEM);

    prep_lm<<<dim3(LL / 32, LL / 32), dim3(32, 8)>>>(mask);
    prep_split<<<dim3((BB * LL * DDIM) / 4 / 256, 3), 256>>>(Q, K, V);

    p1_kernel<<<dim3(LL / 128, BB), 256, P1_SMEM>>>();
    p2_kernel<<<dim3(LL / 128, BB), 256, P2_SMEM>>>(out);
}